// round 10
// baseline (speedup 1.0000x reference)
#include <cuda_runtime.h>

#define FDIM 128
#define DEG 16
#define MAXN 65536
#define EPS 1e-12f

// Scratch: per-node inverse L2 norm (allocation-free rule -> __device__ global)
__device__ float g_rn[MAXN];

__device__ __forceinline__ float warp_sum(float p) {
#pragma unroll
    for (int o = 16; o; o >>= 1) p += __shfl_xor_sync(0xffffffffu, p, o);
    return p;
}

// ---------------------------------------------------------------------------
// Kernel 1: per-node inverse norm. One warp per node, float4 per lane.
// ---------------------------------------------------------------------------
__global__ void norm_kernel(const float* __restrict__ x, int n) {
    int warp = (blockIdx.x * blockDim.x + threadIdx.x) >> 5;
    int lane = threadIdx.x & 31;
    if (warp >= n) return;
    const float4* xr = reinterpret_cast<const float4*>(x + (size_t)warp * FDIM);
    float4 v = xr[lane];
    float s = warp_sum(v.x * v.x + v.y * v.y + v.z * v.z + v.w * v.w);
    if (lane == 0) g_rn[warp] = rsqrtf(s + EPS);
}

// ---------------------------------------------------------------------------
// Kernel 2: AGNN, one warp per node, neighbors in QUADS.
//  - quad-fold shuffle reduction (7 shfl + 4 bcast per 4 neighbors)
//  - -|beta| shift instead of max pass; one __expf per lane per quad
//  - ONE g_rn load per lane (group-selected id, L2 broadcast)
//  - reg budget 36 (launch_bounds 256,7; occ cap 87.5%)
// ---------------------------------------------------------------------------
__global__ __launch_bounds__(256, 7) void agnn_kernel(
    const float* __restrict__ x,
    const int*   __restrict__ col_id,
    const float* __restrict__ beta,
    float*       __restrict__ out,
    int n)
{
    int warp = (blockIdx.x * blockDim.x + threadIdx.x) >> 5;
    int lane = threadIdx.x & 31;
    if (warp >= n) return;

    float b    = beta[0];
    float babs = fabsf(b);
    bool  b4   = (lane & 16) != 0;
    bool  b3   = (lane & 8)  != 0;

    const float4* xv = reinterpret_cast<const float4*>(x);   // row = 32 float4
    float4 vi = xv[((unsigned)warp << 5) + lane];
    float  kq = b * g_rn[warp];
    float4 vip = make_float4(vi.x * kq, vi.y * kq, vi.z * kq, vi.w * kq);

    // Fixed degree: this node's 16 indices start at warp*DEG (64B aligned).
    const int4* cidx = reinterpret_cast<const int4*>(col_id) + ((unsigned)warp << 2);

    float  s   = 0.0f;
    float4 acc = make_float4(0.f, 0.f, 0.f, 0.f);

#pragma unroll
    for (int qd = 0; qd < DEG / 4; qd++) {
        int4 c = __ldg(&cidx[qd]);
        float4 v0 = xv[((unsigned)c.x << 5) + lane];
        float4 v1 = xv[((unsigned)c.y << 5) + lane];
        float4 v2 = xv[((unsigned)c.z << 5) + lane];
        float4 v3 = xv[((unsigned)c.w << 5) + lane];

        // Group-owned neighbor id: (b4,b3) -> (0,0)=c.x (0,1)=c.z (1,0)=c.y (1,1)=c.w
        int   csel  = b4 ? (b3 ? c.w : c.y) : (b3 ? c.z : c.x);
        float rnsel = __ldg(&g_rn[csel]);   // 8-lane group shares one address

        float p0 = vip.x * v0.x + vip.y * v0.y + vip.z * v0.z + vip.w * v0.w;
        float p1 = vip.x * v1.x + vip.y * v1.y + vip.z * v1.z + vip.w * v1.w;
        float p2 = vip.x * v2.x + vip.y * v2.y + vip.z * v2.z + vip.w * v2.w;
        float p3 = vip.x * v3.x + vip.y * v3.y + vip.z * v3.z + vip.w * v3.w;

        // Fold at offset 16: low half keeps p0/p2 partials, high half p1/p3.
        float u = (b4 ? p1 : p0) + __shfl_xor_sync(0xffffffffu, b4 ? p0 : p1, 16);
        float v = (b4 ? p3 : p2) + __shfl_xor_sync(0xffffffffu, b4 ? p2 : p3, 16);
        // Fold at offset 8 -> each 8-lane group owns one neighbor's partial.
        float q = (b3 ? v : u) + __shfl_xor_sync(0xffffffffu, b3 ? u : v, 8);
        // Shared butterfly within 8-lane groups.
        q += __shfl_xor_sync(0xffffffffu, q, 4);
        q += __shfl_xor_sync(0xffffffffu, q, 2);
        q += __shfl_xor_sync(0xffffffffu, q, 1);

        float e = fmaf(q, rnsel, -babs);   // beta*cos - |beta| <= 0
        float w = __expf(e);

        float w0 = __shfl_sync(0xffffffffu, w, 0);
        float w2 = __shfl_sync(0xffffffffu, w, 8);
        float w1 = __shfl_sync(0xffffffffu, w, 16);
        float w3 = __shfl_sync(0xffffffffu, w, 24);

        s += (w0 + w1) + (w2 + w3);
        acc.x = fmaf(w0, v0.x, fmaf(w1, v1.x, fmaf(w2, v2.x, fmaf(w3, v3.x, acc.x))));
        acc.y = fmaf(w0, v0.y, fmaf(w1, v1.y, fmaf(w2, v2.y, fmaf(w3, v3.y, acc.y))));
        acc.z = fmaf(w0, v0.z, fmaf(w1, v1.z, fmaf(w2, v2.z, fmaf(w3, v3.z, acc.z))));
        acc.w = fmaf(w0, v0.w, fmaf(w1, v1.w, fmaf(w2, v2.w, fmaf(w3, v3.w, acc.w))));
    }

    float inv = 1.0f / s;
    float4 o = make_float4(acc.x * inv, acc.y * inv, acc.z * inv, acc.w * inv);
    reinterpret_cast<float4*>(out)[((unsigned)warp << 5) + lane] = o;
}

// ---------------------------------------------------------------------------
// Launch
// ---------------------------------------------------------------------------
extern "C" void kernel_launch(void* const* d_in, const int* in_sizes, int n_in,
                              void* d_out, int out_size) {
    const float* x       = (const float*)d_in[0];
    // d_in[1] = row_id (COO), d_in[2] = row_ptr — fixed degree, base = node*16
    const int*   col_id  = (const int*)d_in[3];
    const float* beta    = (const float*)d_in[4];
    float*       out     = (float*)d_out;

    int n = in_sizes[2] - 1;   // row_ptr has N+1 entries
    if (n > MAXN) n = MAXN;    // defensive: scratch bound (no-op for this shape)

    int threads = 256;
    int blocks  = (n * 32 + threads - 1) / threads;

    norm_kernel<<<blocks, threads>>>(x, n);
    agnn_kernel<<<blocks, threads>>>(x, col_id, beta, out, n);
}

// round 11
// speedup vs baseline: 1.2162x; 1.2162x over previous
#include <cuda_runtime.h>

#define FDIM 128
#define DEG 16
#define MAXN 65536
#define EPS 1e-12f

// Scratch: per-node inverse L2 norm (allocation-free rule -> __device__ global)
__device__ float g_rn[MAXN];

__device__ __forceinline__ float warp_sum(float p) {
#pragma unroll
    for (int o = 16; o; o >>= 1) p += __shfl_xor_sync(0xffffffffu, p, o);
    return p;
}

// ---------------------------------------------------------------------------
// Kernel 1: per-node inverse norm. One warp per node, float4 per lane.
// ---------------------------------------------------------------------------
__global__ void norm_kernel(const float* __restrict__ x, int n) {
    int warp = (blockIdx.x * blockDim.x + threadIdx.x) >> 5;
    int lane = threadIdx.x & 31;
    if (warp >= n) return;
    const float4* xr = reinterpret_cast<const float4*>(x + (size_t)warp * FDIM);
    float4 v = xr[lane];
    float s = warp_sum(v.x * v.x + v.y * v.y + v.z * v.z + v.w * v.w);
    if (lane == 0) g_rn[warp] = rsqrtf(s + EPS);
}

// ---------------------------------------------------------------------------
// Kernel 2: AGNN, one warp per node, neighbors in PAIRS.
//  Pair scheme chosen for its small live set (2 neighbor float4s) so the
//  natural liveness fits a 36-reg budget WITHOUT spilling -> occ tier 87.5%.
//  - fold pair partials at offset 16, 4 shared butterfly steps (7 shfl/pair)
//  - -|beta| shift instead of max pass; one __expf per lane per pair
//  - ONE g_rn load per lane (half-selected id, L2 broadcast)
// ---------------------------------------------------------------------------
__global__ __launch_bounds__(256, 7) void agnn_kernel(
    const float* __restrict__ x,
    const int*   __restrict__ col_id,
    const float* __restrict__ beta,
    float*       __restrict__ out,
    int n)
{
    int warp = (blockIdx.x * blockDim.x + threadIdx.x) >> 5;
    int lane = threadIdx.x & 31;
    if (warp >= n) return;

    float b    = beta[0];
    float babs = fabsf(b);
    bool  hi   = (lane & 16) != 0;

    const float4* xv = reinterpret_cast<const float4*>(x);   // row = 32 float4
    float4 vi = xv[((unsigned)warp << 5) + lane];
    float  kq = b * g_rn[warp];
    float4 vip = make_float4(vi.x * kq, vi.y * kq, vi.z * kq, vi.w * kq);

    // Fixed degree: this node's 16 indices start at warp*DEG (64B aligned).
    const int2* cidx = reinterpret_cast<const int2*>(col_id) + ((unsigned)warp << 3);

    float  s   = 0.0f;
    float4 acc = make_float4(0.f, 0.f, 0.f, 0.f);

#pragma unroll
    for (int p = 0; p < DEG / 2; p++) {
        int2 c = __ldg(&cidx[p]);
        float4 va = xv[((unsigned)c.x << 5) + lane];
        float4 vb = xv[((unsigned)c.y << 5) + lane];

        // Half-owned neighbor id: low half (lanes 0-15) -> c.x, high -> c.y
        float rnsel = __ldg(&g_rn[hi ? c.y : c.x]);   // one bcast load per half

        float pa = vip.x * va.x + vip.y * va.y + vip.z * va.z + vip.w * va.w;
        float pb = vip.x * vb.x + vip.y * vb.y + vip.z * vb.z + vip.w * vb.w;

        // Fold at offset 16: low half keeps pa's partial, high half pb's.
        float q = (hi ? pb : pa) + __shfl_xor_sync(0xffffffffu, hi ? pa : pb, 16);
        // Shared butterfly within each 16-lane half.
        q += __shfl_xor_sync(0xffffffffu, q, 8);
        q += __shfl_xor_sync(0xffffffffu, q, 4);
        q += __shfl_xor_sync(0xffffffffu, q, 2);
        q += __shfl_xor_sync(0xffffffffu, q, 1);

        float e = fmaf(q, rnsel, -babs);   // beta*cos - |beta| <= 0
        float w = __expf(e);

        float wa = __shfl_sync(0xffffffffu, w, 0);
        float wb = __shfl_sync(0xffffffffu, w, 16);

        s += wa + wb;
        acc.x = fmaf(wa, va.x, fmaf(wb, vb.x, acc.x));
        acc.y = fmaf(wa, va.y, fmaf(wb, vb.y, acc.y));
        acc.z = fmaf(wa, va.z, fmaf(wb, vb.z, acc.z));
        acc.w = fmaf(wa, va.w, fmaf(wb, vb.w, acc.w));
    }

    float inv = 1.0f / s;
    float4 o = make_float4(acc.x * inv, acc.y * inv, acc.z * inv, acc.w * inv);
    reinterpret_cast<float4*>(out)[((unsigned)warp << 5) + lane] = o;
}

// ---------------------------------------------------------------------------
// Launch
// ---------------------------------------------------------------------------
extern "C" void kernel_launch(void* const* d_in, const int* in_sizes, int n_in,
                              void* d_out, int out_size) {
    const float* x       = (const float*)d_in[0];
    // d_in[1] = row_id (COO), d_in[2] = row_ptr — fixed degree, base = node*16
    const int*   col_id  = (const int*)d_in[3];
    const float* beta    = (const float*)d_in[4];
    float*       out     = (float*)d_out;

    int n = in_sizes[2] - 1;   // row_ptr has N+1 entries
    if (n > MAXN) n = MAXN;    // defensive: scratch bound (no-op for this shape)

    int threads = 256;
    int blocks  = (n * 32 + threads - 1) / threads;

    norm_kernel<<<blocks, threads>>>(x, n);
    agnn_kernel<<<blocks, threads>>>(x, col_id, beta, out, n);
}